// round 12
// baseline (speedup 1.0000x reference)
#include <cuda_runtime.h>

// Problem constants
#define E_ 4
#define B_ 128
#define Q_ 900
#define C_ 256
#define H_ 16
#define QC_ (Q_ * C_)          // 230400
#define QC4_ (QC_ / 4)         // 57600 float4 per (b)

#define SPLIT_ 8               // blocks per (e,b) row in probs pass
#define QCHUNK_ 113            // ceil(900/8)
#define NPROBS_ (E_ * B_ * SPLIT_)   // 4096 blocks

// Combine config: grid (75, B), 256 threads, 3 float4 per thread
#define CB_THREADS_ 256
#define CB_ITERS_ 3
#define CB_BLOCKSX_ (QC4_ / (CB_THREADS_ * CB_ITERS_))   // 75
#define CB_CHUNK_ (CB_THREADS_ * CB_ITERS_)              // 768

// Scratch (no device mallocs allowed)
__device__ float g_partial[NPROBS_];   // partial q-sums per (e,b,part)

// L2-only sector-granular load
__device__ __forceinline__ float ldcg(const float* p) {
    float v;
    asm volatile("ld.global.cg.f32 %0, [%1];" : "=f"(v) : "l"(p));
    return v;
}

// ---------------------------------------------------------------------------
// Kernel A: partial sums of class-0 logits over q.
// grid = E*B*SPLIT blocks of 128 threads; each thread <=1 scattered load.
// ---------------------------------------------------------------------------
__global__ void __launch_bounds__(128) probs_partial_kernel(
    const float* __restrict__ logits) {
    int blk  = blockIdx.x;
    int row  = blk / SPLIT_;         // e*B + b
    int part = blk % SPLIT_;

    int q = part * QCHUNK_ + threadIdx.x;
    float v = 0.0f;
    if (threadIdx.x < QCHUNK_ && q < Q_)
        v = ldcg(logits + (size_t)row * QC_ + (size_t)q * C_);

    #pragma unroll
    for (int o = 16; o > 0; o >>= 1)
        v += __shfl_down_sync(0xffffffffu, v, o);

    __shared__ float ws[4];
    int lane = threadIdx.x & 31;
    int wid  = threadIdx.x >> 5;
    if (lane == 0) ws[wid] = v;
    __syncthreads();
    if (threadIdx.x == 0)
        g_partial[row * SPLIT_ + part] = ws[0] + ws[1] + ws[2] + ws[3];
}

// ---------------------------------------------------------------------------
// Kernel C: inline-gate + streaming combine.
// Every block recomputes the gate for its b from the L2-resident partials
// (deterministic, identical across blocks); blockIdx.x==0 blocks also write
// the small output tails for their b. Then the proven streaming combine:
// grid (75, B), 3 float4/thread, loads front-batched, __ldcs/__stcs.
// ---------------------------------------------------------------------------
__global__ void __launch_bounds__(CB_THREADS_) combine_kernel(
    const float* __restrict__ logits,
    const float* __restrict__ W1,
    const float* __restrict__ b1,
    const float* __restrict__ W2,
    const float* __restrict__ b2,
    float* __restrict__ out) {
    int b = blockIdx.y;
    int tid = threadIdx.x;

    __shared__ float sp[E_ * SPLIT_];   // this b's 32 partials
    __shared__ int   s_i0, s_i1;
    __shared__ float s_w0, s_w1;

    // Parallel fetch of the 32 partials for this b (one L2 round).
    if (tid < E_ * SPLIT_) {
        int e = tid >> 3;       // /SPLIT_
        int s = tid & 7;        // %SPLIT_
        sp[tid] = g_partial[(e * B_ + b) * SPLIT_ + s];
    }
    __syncthreads();

    if (tid == 0) {
        float p[E_];
        #pragma unroll
        for (int e = 0; e < E_; e++) {
            float t = 0.0f;
            #pragma unroll
            for (int s = 0; s < SPLIT_; s++) t += sp[e * SPLIT_ + s];
            float m = t * (1.0f / (float)Q_);
            p[e] = 1.0f / (1.0f + expf(-m));
        }

        float h[H_];
        #pragma unroll
        for (int j = 0; j < H_; j++) {
            float a = b1[j];
            #pragma unroll
            for (int e = 0; e < E_; e++) a += p[e] * W1[e * H_ + j];
            h[j] = fmaxf(a, 0.0f);
        }

        float z[E_];
        #pragma unroll
        for (int e = 0; e < E_; e++) {
            float a = b2[e];
            #pragma unroll
            for (int j = 0; j < H_; j++) a += h[j] * W2[j * E_ + e];
            z[e] = a;
        }

        float m = fmaxf(fmaxf(z[0], z[1]), fmaxf(z[2], z[3]));
        float w[E_], s = 0.0f;
        #pragma unroll
        for (int e = 0; e < E_; e++) { w[e] = expf(z[e] - m); s += w[e]; }
        float inv = 1.0f / s;
        #pragma unroll
        for (int e = 0; e < E_; e++) w[e] *= inv;

        int i0 = 0;
        #pragma unroll
        for (int e = 1; e < E_; e++) if (w[e] > w[i0]) i0 = e;
        int i1 = -1;
        #pragma unroll
        for (int e = 0; e < E_; e++) {
            if (e == i0) continue;
            if (i1 < 0 || w[e] > w[i1]) i1 = e;
        }

        float ms = w[i0] + w[i1];
        float rn = 1.0f / (ms + 1e-8f);
        float n0 = w[i0] * rn;
        float n1 = w[i1] * rn;

        s_i0 = i0; s_i1 = i1; s_w0 = n0; s_w1 = n1;

        // Tails: [combined | final_pred | norm_w | expert_probs | top_idx]
        if (blockIdx.x == 0) {
            float* fp = out + (size_t)B_ * QC_;
            float* nw = fp + B_;
            float* ep = nw + B_ * E_;
            float* ti = ep + B_ * E_;
            fp[b] = n0 * p[i0] + n1 * p[i1];
            #pragma unroll
            for (int e = 0; e < E_; e++) {
                nw[b * E_ + e] = (e == i0) ? n0 : ((e == i1) ? n1 : 0.0f);
                ep[b * E_ + e] = p[e];
            }
            ti[b * 2 + 0] = (float)i0;
            ti[b * 2 + 1] = (float)i1;
        }
    }
    __syncthreads();

    int i0 = s_i0, i1 = s_i1;
    float w0 = s_w0, w1 = s_w1;

    int base = blockIdx.x * CB_CHUNK_ + tid;   // within [0, QC4)
    const float4* a0 = (const float4*)logits + (size_t)(i0 * B_ + b) * QC4_;
    const float4* a1 = (const float4*)logits + (size_t)(i1 * B_ + b) * QC4_;
    float4* o = (float4*)out + (size_t)b * QC4_;

    float4 x[CB_ITERS_], y[CB_ITERS_];
    #pragma unroll
    for (int k = 0; k < CB_ITERS_; k++)
        x[k] = __ldcs(a0 + base + k * CB_THREADS_);
    #pragma unroll
    for (int k = 0; k < CB_ITERS_; k++)
        y[k] = __ldcs(a1 + base + k * CB_THREADS_);

    #pragma unroll
    for (int k = 0; k < CB_ITERS_; k++) {
        float4 r;
        r.x = w0 * x[k].x + w1 * y[k].x;
        r.y = w0 * x[k].y + w1 * y[k].y;
        r.z = w0 * x[k].z + w1 * y[k].z;
        r.w = w0 * x[k].w + w1 * y[k].w;
        __stcs(o + base + k * CB_THREADS_, r);
    }
}

extern "C" void kernel_launch(void* const* d_in, const int* in_sizes, int n_in,
                              void* d_out, int out_size) {
    const float* logits = (const float*)d_in[0];
    const float* W1     = (const float*)d_in[1];
    const float* b1     = (const float*)d_in[2];
    const float* W2     = (const float*)d_in[3];
    const float* b2     = (const float*)d_in[4];
    float* out = (float*)d_out;

    probs_partial_kernel<<<NPROBS_, 128>>>(logits);
    combine_kernel<<<dim3(CB_BLOCKSX_, B_), CB_THREADS_>>>(logits, W1, b1, W2, b2, out);
}

// round 14
// speedup vs baseline: 1.0306x; 1.0306x over previous
#include <cuda_runtime.h>

// Problem constants
#define E_ 4
#define B_ 128
#define Q_ 900
#define C_ 256
#define H_ 16
#define QC_ (Q_ * C_)          // 230400
#define QC4_ (QC_ / 4)         // 57600 float4 per (b)

#define SPLIT_ 8               // blocks per (e,b) row in probs pass
#define QCHUNK_ 113            // ceil(900/8)
#define NPROBS_ (E_ * B_ * SPLIT_)   // 4096 blocks

// Combine config: grid (45, B), 256 threads, 5 float4 per thread
#define CB_THREADS_ 256
#define CB_ITERS_ 5
#define CB_BLOCKSX_ (QC4_ / (CB_THREADS_ * CB_ITERS_))   // 45
#define CB_CHUNK_ (CB_THREADS_ * CB_ITERS_)              // 1280

// Scratch (no device mallocs allowed)
__device__ float g_partial[NPROBS_];   // partial q-sums per (e,b,part)
__device__ int   g_idx[B_ * 2];        // top-2 indices per b
__device__ float g_w[B_ * 2];          // renormalized top-2 weights per b

// L2-only sector-granular load (avoid nc/tex-path 128B line fill).
__device__ __forceinline__ float ldcg(const float* p) {
    float v;
    asm volatile("ld.global.cg.f32 %0, [%1];" : "=f"(v) : "l"(p));
    return v;
}

// ---------------------------------------------------------------------------
// Kernel A: partial sums of class-0 logits over q.
// grid = E*B*SPLIT blocks of 128 threads; each thread does <=1 scattered load
// via ld.global.cg. (Proven 13.6us configuration — unchanged from R10.)
// ---------------------------------------------------------------------------
__global__ void __launch_bounds__(128) probs_partial_kernel(
    const float* __restrict__ logits) {
    int blk  = blockIdx.x;
    int row  = blk / SPLIT_;         // e*B + b
    int part = blk % SPLIT_;

    int q = part * QCHUNK_ + threadIdx.x;
    float v = 0.0f;
    if (threadIdx.x < QCHUNK_ && q < Q_)
        v = ldcg(logits + (size_t)row * QC_ + (size_t)q * C_);

    #pragma unroll
    for (int o = 16; o > 0; o >>= 1)
        v += __shfl_down_sync(0xffffffffu, v, o);

    __shared__ float ws[4];
    int lane = threadIdx.x & 31;
    int wid  = threadIdx.x >> 5;
    if (lane == 0) ws[wid] = v;
    __syncthreads();
    if (threadIdx.x == 0)
        g_partial[row * SPLIT_ + part] = ws[0] + ws[1] + ws[2] + ws[3];
}

// ---------------------------------------------------------------------------
// Kernel B: finish reduction -> sigmoid -> gating MLP + softmax + top-2.
// One thread per b. Also writes the small output tails. (Unchanged.)
// ---------------------------------------------------------------------------
__global__ void gate_kernel(const float* __restrict__ W1,
                            const float* __restrict__ b1,
                            const float* __restrict__ W2,
                            const float* __restrict__ b2,
                            float* __restrict__ out) {
    int b = threadIdx.x;
    if (b >= B_) return;

    float p[E_];
    #pragma unroll
    for (int e = 0; e < E_; e++) {
        float t = 0.0f;
        #pragma unroll
        for (int s = 0; s < SPLIT_; s++)
            t += g_partial[(e * B_ + b) * SPLIT_ + s];
        float m = t * (1.0f / (float)Q_);
        p[e] = 1.0f / (1.0f + expf(-m));
    }

    float h[H_];
    #pragma unroll
    for (int j = 0; j < H_; j++) {
        float a = b1[j];
        #pragma unroll
        for (int e = 0; e < E_; e++) a += p[e] * W1[e * H_ + j];
        h[j] = fmaxf(a, 0.0f);
    }

    float z[E_];
    #pragma unroll
    for (int e = 0; e < E_; e++) {
        float a = b2[e];
        #pragma unroll
        for (int j = 0; j < H_; j++) a += h[j] * W2[j * E_ + e];
        z[e] = a;
    }

    float m = fmaxf(fmaxf(z[0], z[1]), fmaxf(z[2], z[3]));
    float w[E_], s = 0.0f;
    #pragma unroll
    for (int e = 0; e < E_; e++) { w[e] = expf(z[e] - m); s += w[e]; }
    float inv = 1.0f / s;
    #pragma unroll
    for (int e = 0; e < E_; e++) w[e] *= inv;

    int i0 = 0;
    #pragma unroll
    for (int e = 1; e < E_; e++) if (w[e] > w[i0]) i0 = e;
    int i1 = -1;
    #pragma unroll
    for (int e = 0; e < E_; e++) {
        if (e == i0) continue;
        if (i1 < 0 || w[e] > w[i1]) i1 = e;
    }

    float ms = w[i0] + w[i1];
    float rn = 1.0f / (ms + 1e-8f);
    float n0 = w[i0] * rn;
    float n1 = w[i1] * rn;

    g_idx[b * 2 + 0] = i0;
    g_idx[b * 2 + 1] = i1;
    g_w[b * 2 + 0] = n0;
    g_w[b * 2 + 1] = n1;

    // Output tail layout: [combined | final_pred | norm_w | expert_probs | top_idx]
    float* fp = out + (size_t)B_ * QC_;
    float* nw = fp + B_;
    float* ep = nw + B_ * E_;
    float* ti = ep + B_ * E_;

    fp[b] = n0 * p[i0] + n1 * p[i1];
    #pragma unroll
    for (int e = 0; e < E_; e++) {
        nw[b * E_ + e] = (e == i0) ? n0 : ((e == i1) ? n1 : 0.0f);
        ep[b * E_ + e] = p[e];
    }
    ti[b * 2 + 0] = (float)i0;
    ti[b * 2 + 1] = (float)i1;
}

// ---------------------------------------------------------------------------
// Kernel C: combined[b,q,c] = n0 * logits[i0,b,q,c] + n1 * logits[i1,b,q,c]
// grid (45, B): b uniform per block, 5 float4 per thread, all 10 LDG.128
// front-batched, streaming loads/stores. 45*256*5 = 57600 float4 per b.
// ---------------------------------------------------------------------------
__global__ void __launch_bounds__(CB_THREADS_) combine_kernel(
    const float* __restrict__ logits, float* __restrict__ out) {
    int b = blockIdx.y;
    int base = blockIdx.x * CB_CHUNK_ + threadIdx.x;   // within [0, QC4)

    int i0 = g_idx[b * 2 + 0];
    int i1 = g_idx[b * 2 + 1];
    float w0 = g_w[b * 2 + 0];
    float w1 = g_w[b * 2 + 1];

    const float4* a0 = (const float4*)logits + (size_t)(i0 * B_ + b) * QC4_;
    const float4* a1 = (const float4*)logits + (size_t)(i1 * B_ + b) * QC4_;
    float4* o = (float4*)out + (size_t)b * QC4_;

    float4 x[CB_ITERS_], y[CB_ITERS_];
    #pragma unroll
    for (int k = 0; k < CB_ITERS_; k++)
        x[k] = __ldcs(a0 + base + k * CB_THREADS_);
    #pragma unroll
    for (int k = 0; k < CB_ITERS_; k++)
        y[k] = __ldcs(a1 + base + k * CB_THREADS_);

    #pragma unroll
    for (int k = 0; k < CB_ITERS_; k++) {
        float4 r;
        r.x = w0 * x[k].x + w1 * y[k].x;
        r.y = w0 * x[k].y + w1 * y[k].y;
        r.z = w0 * x[k].z + w1 * y[k].z;
        r.w = w0 * x[k].w + w1 * y[k].w;
        __stcs(o + base + k * CB_THREADS_, r);
    }
}

extern "C" void kernel_launch(void* const* d_in, const int* in_sizes, int n_in,
                              void* d_out, int out_size) {
    const float* logits = (const float*)d_in[0];
    const float* W1     = (const float*)d_in[1];
    const float* b1     = (const float*)d_in[2];
    const float* W2     = (const float*)d_in[3];
    const float* b2     = (const float*)d_in[4];
    float* out = (float*)d_out;

    probs_partial_kernel<<<NPROBS_, 128>>>(logits);
    gate_kernel<<<1, B_>>>(W1, b1, W2, b2, out);
    combine_kernel<<<dim3(CB_BLOCKSX_, B_), CB_THREADS_>>>(logits, out);
}